// round 16
// baseline (speedup 1.0000x reference)
#include <cuda_runtime.h>
#include <cuda_fp16.h>
#include <cstdint>

// Problem constants (B=8, S=512 -> N=4096 tokens)
#define N_TOK   4096
#define H_DIM   512
#define V_DIM   32000
#define DEPTH_EMBED_SCALE 0.01f
#define SIB_SCALE_F 0.04419417382415922f   // (float)(1/sqrt(512))

// Scratch (no allocations -> __device__ globals)
__device__ float  g_h0[N_TOK * H_DIM];
__device__ float  g_c1[N_TOK * 2 * H_DIM];
__device__ float  g_c2[N_TOK * 4 * H_DIM];
__device__ float  g_d3[N_TOK * 4 * H_DIM];
__device__ __half g_h0h[N_TOK * H_DIM];
__device__ __half g_c1h[N_TOK * 2 * H_DIM];
__device__ __half g_c2h[N_TOK * 4 * H_DIM];
__device__ __half g_pooled_h[N_TOK * H_DIM];
__device__ __half g_A0h[N_TOK * H_DIM];
__device__ __half g_Wp_h[H_DIM * H_DIM];
__device__ __half g_Wc_h[H_DIM * 1024];
__device__ __half g_W2h[H_DIM * H_DIM];
__device__ __half g_WoutH[(size_t)H_DIM * V_DIM];   // fp16 Wout [K][V]
__device__ float  g_b2[H_DIM];
// Gate composite precompute
__device__ float  g_uL[H_DIM], g_uR[H_DIM], g_bL[H_DIM], g_bR[H_DIM];
__device__ float  g_cols[7][H_DIM];
__device__ float  g_GG[7][H_DIM];
__device__ double g_kc[7];
__device__ double g_dots[16];

__device__ __forceinline__ void cp16(void* s, const void* g) {
    unsigned saddr = (unsigned)__cvta_generic_to_shared(s);
    asm volatile("cp.async.cg.shared.global [%0], [%1], 16;\n" :: "r"(saddr), "l"(g));
}

// ---------------------------------------------------------------------------
// Fused prep kernel: block-range dispatch over 6 independent jobs
// (incl. gate-chain stage g1).
// ---------------------------------------------------------------------------
#define PB_WOUT   8000
#define PB_WC     (PB_WOUT + 256)
#define PB_WP     (PB_WC + 128)
#define PB_W2     (PB_WP + 1024)
#define PB_GATHER (PB_W2 + 1024)
#define PB_G1     (PB_GATHER + 512)

__device__ __forceinline__ void cvt8(const float* __restrict__ src,
                                     __half* __restrict__ dst, int i)
{
    float4 a = ((const float4*)src)[2 * i];
    float4 b = ((const float4*)src)[2 * i + 1];
    __half2 h0 = __floats2half2_rn(a.x, a.y);
    __half2 h1 = __floats2half2_rn(a.z, a.w);
    __half2 h2 = __floats2half2_rn(b.x, b.y);
    __half2 h3 = __floats2half2_rn(b.z, b.w);
    uint4 o;
    o.x = *(uint32_t*)&h0; o.y = *(uint32_t*)&h1;
    o.z = *(uint32_t*)&h2; o.w = *(uint32_t*)&h3;
    ((uint4*)dst)[i] = o;
}

__global__ __launch_bounds__(256)
void prep_misc(const float* __restrict__ Wout, const float* __restrict__ Wc,
               const float* __restrict__ Wp, const float* __restrict__ bc,
               const float* __restrict__ sib, const int* __restrict__ tokens,
               const float* __restrict__ emb, const float* __restrict__ Wg)
{
    const int bid = blockIdx.x, t = threadIdx.x;
    __shared__ double s[2][256];
    if (bid < PB_WOUT) {
        cvt8(Wout, g_WoutH, bid * 256 + t);
    } else if (bid < PB_WC) {
        cvt8(Wc, g_Wc_h, (bid - PB_WOUT) * 256 + t);
    } else if (bid < PB_WP) {
        cvt8(Wp, g_Wp_h, (bid - PB_WC) * 256 + t);
    } else if (bid < PB_W2) {
        int i = (bid - PB_WP) * 256 + t;
        int h = i >> 9, j = i & 511;
        g_W2h[i] = __float2half_rn(Wc[(size_t)h * 1024 + j] + Wc[(size_t)h * 1024 + 512 + j]);
        if (i < H_DIM)
            g_b2[i] = bc[i] + bc[512 + i] + SIB_SCALE_F * (sib[i] + sib[512 + i]);
    } else if (bid < PB_GATHER) {
        int i = (bid - PB_W2) * 256 + t;
        int n = i >> 6;
        int c = (i & 63) * 8;
        const float* src = emb + (size_t)tokens[n] * H_DIM + c;
        float4 a = *(const float4*)src;
        float4 b = *(const float4*)(src + 4);
        __half2 h0 = __floats2half2_rn(a.x, a.y);
        __half2 h1 = __floats2half2_rn(a.z, a.w);
        __half2 h2 = __floats2half2_rn(b.x, b.y);
        __half2 h3 = __floats2half2_rn(b.z, b.w);
        uint4 o;
        o.x = *(uint32_t*)&h0; o.y = *(uint32_t*)&h1;
        o.z = *(uint32_t*)&h2; o.w = *(uint32_t*)&h3;
        ((uint4*)(g_A0h + (size_t)n * H_DIM + c))[0] = o;
    } else {
        // gate stage g1: uL/uR/bL/bR
        const int h = bid - PB_GATHER;
        double aL = 0.0, aR = 0.0;
        for (int j = t; j < H_DIM; j += 256) {
            double w = (double)Wg[j];
            aL += (double)Wc[(size_t)h * 1024 + j]       * w;
            aR += (double)Wc[(size_t)h * 1024 + 512 + j] * w;
        }
        s[0][t] = aL; s[1][t] = aR;
        __syncthreads();
        for (int st = 128; st > 0; st >>= 1) {
            if (t < st) { s[0][t] += s[0][t + st]; s[1][t] += s[1][t + st]; }
            __syncthreads();
        }
        if (t == 0) {
            g_uL[h] = (float)s[0][0];
            g_uR[h] = (float)s[1][0];
            g_bL[h] = bc[h]       + SIB_SCALE_F * sib[h];
            g_bR[h] = bc[512 + h] + SIB_SCALE_F * sib[512 + h];
        }
    }
}

// ---------------------------------------------------------------------------
// Gate chain stage 2: cols[0..6] + GG[0..2]
// ---------------------------------------------------------------------------
__global__ __launch_bounds__(256)
void prep_g23(const float* __restrict__ Wc, const float* __restrict__ Wg,
              const float* __restrict__ Wp)
{
    const int bid = blockIdx.x, t = threadIdx.x;
    __shared__ double s[4][256];
    if (bid < H_DIM) {
        const int h = bid;
        double a3 = 0.0, a4 = 0.0, a5 = 0.0, a6 = 0.0;
        for (int j = t; j < H_DIM; j += 256) {
            double ul = (double)g_uL[j], ur = (double)g_uR[j];
            double wl = (double)Wc[(size_t)h * 1024 + j];
            double wr = (double)Wc[(size_t)h * 1024 + 512 + j];
            a3 += wl * ul; a4 += wl * ur; a5 += wr * ul; a6 += wr * ur;
        }
        s[0][t] = a3; s[1][t] = a4; s[2][t] = a5; s[3][t] = a6;
        __syncthreads();
        for (int st = 128; st > 0; st >>= 1) {
            if (t < st)
                #pragma unroll
                for (int q = 0; q < 4; q++) s[q][t] += s[q][t + st];
            __syncthreads();
        }
        if (t == 0) {
            g_cols[0][h] = Wg[h];
            g_cols[1][h] = g_uL[h];
            g_cols[2][h] = g_uR[h];
            g_cols[3][h] = (float)s[0][0];
            g_cols[4][h] = (float)s[1][0];
            g_cols[5][h] = (float)s[2][0];
            g_cols[6][h] = (float)s[3][0];
        }
    } else {
        const int e = bid - H_DIM;
        double a0 = 0.0, a1 = 0.0, a2 = 0.0;
        for (int h = t; h < H_DIM; h += 256) {
            double w = (double)Wp[(size_t)e * H_DIM + h];
            a0 += w * (double)Wg[h];
            a1 += w * (double)g_uL[h];
            a2 += w * (double)g_uR[h];
        }
        s[0][t] = a0; s[1][t] = a1; s[2][t] = a2;
        __syncthreads();
        for (int st = 128; st > 0; st >>= 1) {
            if (t < st)
                #pragma unroll
                for (int q = 0; q < 3; q++) s[q][t] += s[q][t + st];
            __syncthreads();
        }
        if (t == 0) {
            g_GG[0][e] = (float)s[0][0];
            g_GG[1][e] = (float)s[1][0];
            g_GG[2][e] = (float)s[2][0];
        }
    }
}

// ---------------------------------------------------------------------------
// Gate chain stage 3: GG[3..6] (blocks 0..511) + 16 scalar dots (512..527)
// ---------------------------------------------------------------------------
__global__ __launch_bounds__(256)
void prep_g3c(const float* __restrict__ Wp, const float* __restrict__ Wg,
              const float* __restrict__ dep, const float* __restrict__ bp)
{
    const int bid = blockIdx.x, t = threadIdx.x;
    if (bid < H_DIM) {
        const int e = bid;
        __shared__ double s4[4][256];
        double a[4] = {0, 0, 0, 0};
        for (int h = t; h < H_DIM; h += 256) {
            double w = (double)Wp[(size_t)e * H_DIM + h];
            #pragma unroll
            for (int i = 0; i < 4; i++) a[i] += w * (double)g_cols[3 + i][h];
        }
        #pragma unroll
        for (int i = 0; i < 4; i++) s4[i][t] = a[i];
        __syncthreads();
        for (int st = 128; st > 0; st >>= 1) {
            if (t < st)
                #pragma unroll
                for (int i = 0; i < 4; i++) s4[i][t] += s4[i][t + st];
            __syncthreads();
        }
        if (t == 0)
            #pragma unroll
            for (int i = 0; i < 4; i++) g_GG[3 + i][e] = (float)s4[i][0];
    } else {
        const int d = bid - H_DIM;
        __shared__ double s[256];
        const float* pa[16] = { dep, dep + 512, dep + 1024, g_bL, g_bR,
                                g_bL, g_bL, g_bR, g_bR,
                                bp, bp, bp, bp, bp, bp, bp };
        const float* pb[16] = { Wg, Wg, Wg, Wg, Wg,
                                g_uL, g_uR, g_uL, g_uR,
                                g_cols[0], g_cols[1], g_cols[2], g_cols[3],
                                g_cols[4], g_cols[5], g_cols[6] };
        double acc = 0.0;
        for (int c = t; c < H_DIM; c += 256)
            acc += (double)pa[d][c] * (double)pb[d][c];
        s[t] = acc;
        __syncthreads();
        for (int st = 128; st > 0; st >>= 1) {
            if (t < st) s[t] += s[t + st];
            __syncthreads();
        }
        if (t == 0) g_dots[d] = s[0];
    }
}

__global__ void prep_g4b(const float* __restrict__ bgp)
{
    if (threadIdx.x == 0) {
        const double de = (double)DEPTH_EMBED_SCALE;
        double bg = (double)bgp[0];
        const double* d = g_dots;
        g_kc[0] = de * d[0] + bg + d[9];
        g_kc[1] = d[3] + de * d[1] + bg + d[10];
        g_kc[2] = d[4] + de * d[1] + bg + d[11];
        g_kc[3] = d[5] + d[3] + de * d[2] + bg + d[12];
        g_kc[4] = d[6] + d[4] + de * d[2] + bg + d[13];
        g_kc[5] = d[7] + d[3] + de * d[2] + bg + d[14];
        g_kc[6] = d[8] + d[4] + de * d[2] + bg + d[15];
    }
}

// ---------------------------------------------------------------------------
// ldmatrix / mma macros
// ---------------------------------------------------------------------------
#define LDSM_X4(r0, r1, r2, r3, addr) \
    asm volatile("ldmatrix.sync.aligned.m8n8.x4.shared.b16 {%0,%1,%2,%3}, [%4];" \
        : "=r"(r0), "=r"(r1), "=r"(r2), "=r"(r3) : "r"(addr))
#define LDSM_X4T(r0, r1, r2, r3, addr) \
    asm volatile("ldmatrix.sync.aligned.m8n8.x4.trans.shared.b16 {%0,%1,%2,%3}, [%4];" \
        : "=r"(r0), "=r"(r1), "=r"(r2), "=r"(r3) : "r"(addr))
#define HMMA16816(acc, a, b) \
    asm volatile("mma.sync.aligned.m16n8k16.row.col.f32.f16.f16.f32 " \
        "{%0,%1,%2,%3}, {%4,%5,%6,%7}, {%8,%9}, {%0,%1,%2,%3};" \
        : "+f"((acc)[0]), "+f"((acc)[1]), "+f"((acc)[2]), "+f"((acc)[3]) \
        : "r"((a)[0]), "r"((a)[1]), "r"((a)[2]), "r"((a)[3]), \
          "r"((b)[0]), "r"((b)[1]))

// ---------------------------------------------------------------------------
// Tree fp16 GEMM (unchanged from 760us kernel): 128x128, BK=32, 4-stage ring,
// single sync per k-iter, occ 2.
// ---------------------------------------------------------------------------
#define AS_LD 40
#define BS_LD 136
#define AS4_STG  (128 * AS_LD * 2)
#define BS4_STG  (32 * BS_LD * 2)
#define SM4_B0   (4 * AS4_STG)
#define SM4_TOT  (4 * AS4_STG + 4 * BS4_STG)   // 75776 B

template<int EPI, int WF16>
__global__ __launch_bounds__(256, 2)
void gemm_f16(const __half* __restrict__ A, const __half* __restrict__ B,
              float* __restrict__ C, __half* __restrict__ C16,
              int M, int Ncol, int K,
              const float* __restrict__ bias, const float* __restrict__ sib)
{
    extern __shared__ __half sm4[];

    const int tid  = threadIdx.x;
    const int row0 = blockIdx.y * 128;
    const int col0 = blockIdx.x * 128;
    const int warp = tid >> 5, lane = tid & 31;
    const int gid  = lane >> 2, tg = lane & 3;
    const int wm   = (warp & 1) * 64;
    const int wn   = (warp >> 1) * 32;

    const int ar = tid >> 1;
    const int ac = (tid & 1) * 16;
    const int br = tid >> 3;
    const int bc = (tid & 7) * 16;

    const __half* Ag = A + (size_t)(row0 + ar) * (size_t)K + ac;
    const __half* Bg = B + (size_t)br * (size_t)Ncol + col0 + bc;

    __half* Asm = sm4;
    __half* Bsm = (__half*)((char*)sm4 + SM4_B0);

    const int a_r = lane & 15;
    const int a_c = (lane >> 4) << 3;
    const int b_k = (lane & 7) + (lane & 8);
    const int b_c = (lane >> 4) << 3;

    const uint32_t as_base = (uint32_t)__cvta_generic_to_shared(Asm);
    const uint32_t bs_base = (uint32_t)__cvta_generic_to_shared(Bsm);

    float acc[4][4][4];
    #pragma unroll
    for (int mi = 0; mi < 4; mi++)
        #pragma unroll
        for (int ni = 0; ni < 4; ni++)
            #pragma unroll
            for (int q = 0; q < 4; q++) acc[mi][ni][q] = 0.f;

    const int NT = K / 32;

    auto load_stage = [&](int kt, int buf) {
        const __half* Ap = Ag + (size_t)kt * 32;
        const __half* Bp = Bg + (size_t)kt * 32 * (size_t)Ncol;
        __half* Ad = Asm + buf * (128 * AS_LD) + ar * AS_LD + ac;
        __half* Bd = Bsm + buf * (32 * BS_LD) + br * BS_LD + bc;
        cp16(Ad,     Ap);
        cp16(Ad + 8, Ap + 8);
        cp16(Bd,     Bp);
        cp16(Bd + 8, Bp + 8);
        asm volatile("cp.async.commit_group;\n");
    };

    load_stage(0, 0);
    load_stage(1, 1);
    load_stage(2, 2);

    for (int kt = 0; kt < NT; kt++) {
        const int cur = kt & 3;
        if (kt + 2 < NT)      asm volatile("cp.async.wait_group 2;\n");
        else if (kt + 1 < NT) asm volatile("cp.async.wait_group 1;\n");
        else                  asm volatile("cp.async.wait_group 0;\n");
        __syncthreads();

        const uint32_t asb = as_base + cur * AS4_STG;
        const uint32_t bsb = bs_base + cur * BS4_STG;

        #pragma unroll
        for (int ks = 0; ks < 2; ks++) {
            const int kk = ks * 16;
            uint32_t af[4][4];
            #pragma unroll
            for (int mi = 0; mi < 4; mi++) {
                uint32_t ad = asb + ((wm + mi * 16 + a_r) * AS_LD + kk + a_c) * 2;
                LDSM_X4(af[mi][0], af[mi][1], af[mi][2], af[mi][3], ad);
            }
            uint32_t bf[4][2];
            #pragma unroll
            for (int j = 0; j < 2; j++) {
                uint32_t bd = bsb + ((kk + b_k) * BS_LD + wn + j * 16 + b_c) * 2;
                LDSM_X4T(bf[2 * j][0], bf[2 * j][1], bf[2 * j + 1][0], bf[2 * j + 1][1], bd);
            }
            #pragma unroll
            for (int mi = 0; mi < 4; mi++)
                #pragma unroll
                for (int ni = 0; ni < 4; ni++)
                    HMMA16816(acc[mi][ni], af[mi], bf[ni]);
        }

        if (kt + 3 < NT)
            load_stage(kt + 3, (kt + 3) & 3);
    }

    #pragma unroll
    for (int ni = 0; ni < 4; ni++) {
        int cc = col0 + wn + ni * 8 + tg * 2;
        float b0 = bias[cc], b1 = bias[cc + 1];
        if (EPI == 1) { b0 += SIB_SCALE_F * sib[cc]; b1 += SIB_SCALE_F * sib[cc + 1]; }
        #pragma unroll
        for (int mi = 0; mi < 4; mi++) {
            int r = row0 + wm + mi * 16 + gid;
            float v0 = acc[mi][ni][0] + b0, v1 = acc[mi][ni][1] + b1;
            float v2 = acc[mi][ni][2] + b0, v3 = acc[mi][ni][3] + b1;
            *(float2*)(C + (size_t)r * (size_t)Ncol + cc)       = make_float2(v0, v1);
            *(float2*)(C + (size_t)(r + 8) * (size_t)Ncol + cc) = make_float2(v2, v3);
            if (WF16) {
                *(__half2*)(C16 + (size_t)r * (size_t)Ncol + cc)       = __floats2half2_rn(v0, v1);
                *(__half2*)(C16 + (size_t)(r + 8) * (size_t)Ncol + cc) = __floats2half2_rn(v2, v3);
            }
        }
    }
}

// ---------------------------------------------------------------------------
// Persistent big GEMM (logits): each CTA owns one M-block, A slab (128x512
// fp16) resident in SMEM; streams B over a chain of N-tiles with a 2-stage
// ring (BK=64), single sync per stage. Grid = 32 M-blocks x 4 chains = 128.
// A L2 traffic: 17 MB (vs 1.05 GB tiled). K-order per output unchanged.
// ---------------------------------------------------------------------------
#define NTILES    (V_DIM / 128)     // 250
#define NCHAINS   4
#define ASP_LD    520               // 512 + 8 pad: 65x16B odd stride, LDSM-safe
#define ASP_BYTES (128 * ASP_LD * 2)    // 133120
#define BSP_STG   (64 * BS_LD * 2)      // 17408
#define SMP_B0    ASP_BYTES
#define SMP_TOT   (ASP_BYTES + 2 * BSP_STG)   // 167936

__global__ __launch_bounds__(256, 1)
void gemm_big_persist(const __half* __restrict__ A, const __half* __restrict__ B,
                      float* __restrict__ C, const float* __restrict__ bias)
{
    extern __shared__ __half smp[];
    const int tid   = threadIdx.x;
    const int m     = blockIdx.x & 31;
    const int chain = blockIdx.x >> 5;
    const int row0  = m * 128;
    const int warp = tid >> 5, lane = tid & 31;
    const int gid  = lane >> 2, tg = lane & 3;
    const int wm   = (warp & 1) * 64;
    const int wn   = (warp >> 1) * 32;

    __half* Asm = smp;
    __half* Bsm = (__half*)((char*)smp + SMP_B0);

    // Load A slab: 128 rows x 512 halfs (8192 16B-chunks, 32 per thread)
    #pragma unroll
    for (int i = 0; i < 32; i++) {
        int chunk = i * 256 + tid;
        int r = chunk >> 6, c8 = (chunk & 63) * 8;
        cp16(Asm + r * ASP_LD + c8, A + (size_t)(row0 + r) * H_DIM + c8);
    }
    asm volatile("cp.async.commit_group;\n");

    // B stage mapping: 64 k-rows x 128 cols; 4 threads/row, 4 chunks/thread
    const int br = tid >> 2;
    const int bc = (tid & 3) * 32;

    auto load_b = [&](int n, int kt, int buf) {
        const __half* Bp = B + (size_t)(kt * 64 + br) * V_DIM + n * 128 + bc;
        __half* Bd = Bsm + buf * (64 * BS_LD) + br * BS_LD + bc;
        cp16(Bd,      Bp);
        cp16(Bd + 8,  Bp + 8);
        cp16(Bd + 16, Bp + 16);
        cp16(Bd + 24, Bp + 24);
        asm volatile("cp.async.commit_group;\n");
    };

    const int a_r = lane & 15;
    const int a_c = (lane >> 4) << 3;
    const int b_k = (lane & 7) + (lane & 8);
    const int b_c = (lane >> 4) << 3;

    const uint32_t as_base = (uint32_t)__cvta_generic_to_shared(Asm);
    const uint32_t bs_base = (uint32_t)__cvta_generic_to_shared(Bsm);

    // preload stage 0 of first tile
    load_b(chain, 0, 0);

    int g = 0;   // global stage counter (ring = g & 1)
    for (int n = chain; n < NTILES; n += NCHAINS) {
        float acc[4][4][4];
        #pragma unroll
        for (int mi = 0; mi < 4; mi++)
            #pragma unroll
            for (int ni = 0; ni < 4; ni++)
                #pragma unroll
                for (int q = 0; q < 4; q++) acc[mi][ni][q] = 0.f;

        for (int kt = 0; kt < 8; kt++) {
            const int ring = g & 1;
            asm volatile("cp.async.wait_group 0;\n");
            __syncthreads();

            // prefetch next stage into the other buffer
            if (kt < 7)                       load_b(n, kt + 1, ring ^ 1);
            else if (n + NCHAINS < NTILES)    load_b(n + NCHAINS, 0, ring ^ 1);

            const uint32_t bsb = bs_base + ring * BSP_STG;
            #pragma unroll
            for (int ks = 0; ks < 4; ks++) {
                const int kkB = ks * 16;
                const int kkA = kt * 64 + kkB;
                uint32_t af[4][4];
                #pragma unroll
                for (int mi = 0; mi < 4; mi++) {
                    uint32_t ad = as_base + ((wm + mi * 16 + a_r) * ASP_LD + kkA + a_c) * 2;
                    LDSM_X4(af[mi][0], af[mi][1], af[mi][2], af[mi][3], ad);
                }
                uint32_t bf[4][2];
                #pragma unroll
                for (int j = 0; j < 2; j++) {
                    uint32_t bd = bsb + ((kkB + b_k) * BS_LD + wn + j * 16 + b_c) * 2;
                    LDSM_X4T(bf[2 * j][0], bf[2 * j][1], bf[2 * j + 1][0], bf[2 * j + 1][1], bd);
                }
                #pragma unroll
                for (int mi = 0; mi < 4; mi++)
                    #pragma unroll
                    for (int ni = 0; ni < 4; ni++)
                        HMMA16816(acc[mi][ni], af[mi], bf[ni]);
            }
            g++;
        }

        // epilogue (no smem use; overlaps the in-flight prefetch)
        const int col0 = n * 128;
        #pragma unroll
        for (int ni = 0; ni < 4; ni++) {
            int cc = col0 + wn + ni * 8 + tg * 2;
            float b0 = bias[cc], b1 = bias[cc + 1];
            #pragma unroll
            for (int mi = 0; mi < 4; mi++) {
                int r = row0 + wm + mi * 16 + gid;
                *(float2*)(C + (size_t)r * V_DIM + cc) =
                    make_float2(acc[mi][ni][0] + b0, acc[mi][ni][1] + b1);
                *(float2*)(C + (size_t)(r + 8) * V_DIM + cc) =
                    make_float2(acc[mi][ni][2] + b0, acc[mi][ni][3] + b1);
            }
        }
    }
}

// ---------------------------------------------------------------------------
// Gate + pool kernel (gates via double-precision composite).
// ---------------------------------------------------------------------------
__global__ __launch_bounds__(256)
void pool_kernel(const int* __restrict__ tokens, const float* __restrict__ emb)
{
    const int n = blockIdx.x;
    const int t = threadIdx.x;
    const float* a  = emb + (size_t)tokens[n] * H_DIM;
    const float* H0 = g_h0 + (size_t)n * H_DIM;
    const float* C1 = g_c1 + (size_t)n * (2 * H_DIM);
    const float* C2 = g_c2 + (size_t)n * (4 * H_DIM);
    const float* D3 = g_d3 + (size_t)n * (4 * H_DIM);

    __shared__ double red[7][256];
    double p[7] = {0, 0, 0, 0, 0, 0, 0};
    for (int c = t; c < H_DIM; c += 256) {
        double av = (double)a[c];
        #pragma unroll
        for (int i = 0; i < 7; i++) p[i] += av * (double)g_GG[i][c];
    }
    #pragma unroll
    for (int i = 0; i < 7; i++) red[i][t] = p[i];
    __syncthreads();
    for (int s = 128; s > 0; s >>= 1) {
        if (t < s)
            #pragma unroll
            for (int i = 0; i < 7; i++) red[i][t] += red[i][t + s];
        __syncthreads();
    }

    const bool e0 = (red[0][0] + g_kc[0]) > 0.0;
    bool e1[2], e2[4];
    e1[0] = e0 && ((red[1][0] + g_kc[1]) > 0.0);
    e1[1] = e0 && ((red[2][0] + g_kc[2]) > 0.0);
    e2[0] = e1[0] && ((red[3][0] + g_kc[3]) > 0.0);
    e2[1] = e1[0] && ((red[4][0] + g_kc[4]) > 0.0);
    e2[2] = e1[1] && ((red[5][0] + g_kc[5]) > 0.0);
    e2[3] = e1[1] && ((red[6][0] + g_kc[6]) > 0.0);

    float count = 1.f
        + 2.f * (e0 ? 1.f : 0.f)
        + 2.f * ((e1[0] ? 1.f : 0.f) + (e1[1] ? 1.f : 0.f))
        + 2.f * ((e2[0] ? 1.f : 0.f) + (e2[1] ? 1.f : 0.f) +
                 (e2[2] ? 1.f : 0.f) + (e2[3] ? 1.f : 0.f));
    const float inv = 1.f / fmaxf(count, 1e-8f);

    for (int c = t; c < H_DIM; c += 256) {
        float s = H0[c];
        if (e0)    s += C1[c] + C1[H_DIM + c];
        if (e1[0]) s += C2[c] + C2[H_DIM + c];
        if (e1[1]) s += C2[2 * H_DIM + c] + C2[3 * H_DIM + c];
        if (e2[0]) s += D3[0 * H_DIM + c];
        if (e2[1]) s += D3[1 * H_DIM + c];
        if (e2[2]) s += D3[2 * H_DIM + c];
        if (e2[3]) s += D3[3 * H_DIM + c];
        g_pooled_h[(size_t)n * H_DIM + c] = __float2half_rn(s * inv);
    }
}

// ---------------------------------------------------------------------------
extern "C" void kernel_launch(void* const* d_in, const int* in_sizes, int n_in,
                              void* d_out, int out_size)
{
    const int*   tokens = (const int*)  d_in[0];
    const float* emb    = (const float*)d_in[1];
    const float* Wp     = (const float*)d_in[2];
    const float* bp     = (const float*)d_in[3];
    const float* Wc     = (const float*)d_in[4];
    const float* bc     = (const float*)d_in[5];
    const float* Wg     = (const float*)d_in[6];
    const float* bg     = (const float*)d_in[7];
    const float* dep    = (const float*)d_in[8];
    const float* sib    = (const float*)d_in[9];
    const float* Wout   = (const float*)d_in[10];
    const float* bout   = (const float*)d_in[11];
    float* out = (float*)d_out;

    float  *h0, *c1, *c2, *d3, *b2;
    __half *h0h, *c1h, *c2h, *pooledh, *A0h, *Wp_h, *Wc_h, *W2h, *Wout_h;
    cudaGetSymbolAddress((void**)&h0,      g_h0);
    cudaGetSymbolAddress((void**)&c1,      g_c1);
    cudaGetSymbolAddress((void**)&c2,      g_c2);
    cudaGetSymbolAddress((void**)&d3,      g_d3);
    cudaGetSymbolAddress((void**)&b2,      g_b2);
    cudaGetSymbolAddress((void**)&h0h,     g_h0h);
    cudaGetSymbolAddress((void**)&c1h,     g_c1h);
    cudaGetSymbolAddress((void**)&c2h,     g_c2h);
    cudaGetSymbolAddress((void**)&pooledh, g_pooled_h);
    cudaGetSymbolAddress((void**)&A0h,     g_A0h);
    cudaGetSymbolAddress((void**)&Wp_h,    g_Wp_h);
    cudaGetSymbolAddress((void**)&Wc_h,    g_Wc_h);
    cudaGetSymbolAddress((void**)&W2h,     g_W2h);
    cudaGetSymbolAddress((void**)&Wout_h,  g_WoutH);

    cudaFuncSetAttribute(gemm_f16<0, 1>, cudaFuncAttributeMaxDynamicSharedMemorySize, SM4_TOT);
    cudaFuncSetAttribute(gemm_f16<1, 1>, cudaFuncAttributeMaxDynamicSharedMemorySize, SM4_TOT);
    cudaFuncSetAttribute(gemm_f16<0, 0>, cudaFuncAttributeMaxDynamicSharedMemorySize, SM4_TOT);
    cudaFuncSetAttribute(gemm_big_persist, cudaFuncAttributeMaxDynamicSharedMemorySize, SMP_TOT);

    dim3 blk(256);

    // Preps: fused misc+g1, then g23, then g3b+g4a, then compose
    prep_misc<<<PB_G1, blk>>>(Wout, Wc, Wp, bc, sib, tokens, emb, Wg);
    prep_g23<<<2 * H_DIM, blk>>>(Wc, Wg, Wp);
    prep_g3c<<<H_DIM + 16, blk>>>(Wp, Wg, dep, bp);
    prep_g4b<<<1, 32>>>(bg);

    // Tree (single-sync 4-stage fp16 GEMM, unchanged)
    gemm_f16<0, 1><<<dim3(H_DIM / 128, N_TOK / 128), blk, SM4_TOT>>>(
        A0h, Wp_h, h0, h0h, N_TOK, H_DIM, H_DIM, bp, nullptr);
    gemm_f16<1, 1><<<dim3(1024 / 128, N_TOK / 128), blk, SM4_TOT>>>(
        h0h, Wc_h, c1, c1h, N_TOK, 1024, H_DIM, bc, sib);
    gemm_f16<1, 1><<<dim3(1024 / 128, (2 * N_TOK) / 128), blk, SM4_TOT>>>(
        c1h, Wc_h, c2, c2h, 2 * N_TOK, 1024, H_DIM, bc, sib);
    gemm_f16<0, 0><<<dim3(H_DIM / 128, (4 * N_TOK) / 128), blk, SM4_TOT>>>(
        c2h, W2h, d3, nullptr, 4 * N_TOK, H_DIM, H_DIM, b2, nullptr);

    // Gates + pooling
    pool_kernel<<<N_TOK, blk>>>(tokens, emb);

    // logits: persistent A-resident GEMM (128 CTAs)
    gemm_big_persist<<<32 * NCHAINS, blk, SMP_TOT>>>(pooledh, Wout_h, out, bout);
}

// round 17
// speedup vs baseline: 1.3289x; 1.3289x over previous
#include <cuda_runtime.h>
#include <cuda_fp16.h>
#include <cstdint>

// Problem constants (B=8, S=512 -> N=4096 tokens)
#define N_TOK   4096
#define H_DIM   512
#define V_DIM   32000
#define DEPTH_EMBED_SCALE 0.01f
#define SIB_SCALE_F 0.04419417382415922f   // (float)(1/sqrt(512))

// Scratch (no allocations -> __device__ globals). Tree buffers carry 128
// overflow rows for padded scatter entries.
__device__ float  g_h0[N_TOK * H_DIM];
__device__ float  g_c1[(N_TOK + 128) * 2 * H_DIM];
__device__ float  g_c2[(2 * N_TOK + 128) * 1024];
__device__ float  g_d3[(4 * N_TOK + 128) * H_DIM];
__device__ __half g_h0h[N_TOK * H_DIM];
__device__ __half g_c1h[(N_TOK + 128) * 2 * H_DIM];
__device__ __half g_c2h[(2 * N_TOK + 128) * 1024];
__device__ __half g_pooled_h[N_TOK * H_DIM];
__device__ __half g_A0h[N_TOK * H_DIM];
__device__ __half g_Wp_h[H_DIM * H_DIM];
__device__ __half g_Wc_h[H_DIM * 1024];
__device__ __half g_W2h[H_DIM * H_DIM];
__device__ __half g_WoutH[(size_t)H_DIM * V_DIM];
__device__ float  g_b2[H_DIM];
// Gate composite precompute
__device__ float  g_uL[H_DIM], g_uR[H_DIM], g_bL[H_DIM], g_bR[H_DIM];
__device__ float  g_cols[7][H_DIM];
__device__ float  g_GG[7][H_DIM];
__device__ double g_kc[7];
__device__ double g_dots[16];
// Gating state
__device__ int    g_flags[N_TOK];
__device__ float  g_inv[N_TOK];
__device__ int    g_cnt1, g_cnt2, g_cnt3;
__device__ int    g_pc1, g_pc2, g_pc3;
__device__ int2   g_list1[N_TOK + 128];
__device__ int2   g_list2[2 * N_TOK + 128];
__device__ int2   g_list3[4 * N_TOK + 128];

__device__ __forceinline__ void cp16(void* s, const void* g) {
    unsigned saddr = (unsigned)__cvta_generic_to_shared(s);
    asm volatile("cp.async.cg.shared.global [%0], [%1], 16;\n" :: "r"(saddr), "l"(g));
}

// ---------------------------------------------------------------------------
// Fused prep kernel (incl. gate stage g1)
// ---------------------------------------------------------------------------
#define PB_WOUT   8000
#define PB_WC     (PB_WOUT + 256)
#define PB_WP     (PB_WC + 128)
#define PB_W2     (PB_WP + 1024)
#define PB_GATHER (PB_W2 + 1024)
#define PB_G1     (PB_GATHER + 512)

__device__ __forceinline__ void cvt8(const float* __restrict__ src,
                                     __half* __restrict__ dst, int i)
{
    float4 a = ((const float4*)src)[2 * i];
    float4 b = ((const float4*)src)[2 * i + 1];
    __half2 h0 = __floats2half2_rn(a.x, a.y);
    __half2 h1 = __floats2half2_rn(a.z, a.w);
    __half2 h2 = __floats2half2_rn(b.x, b.y);
    __half2 h3 = __floats2half2_rn(b.z, b.w);
    uint4 o;
    o.x = *(uint32_t*)&h0; o.y = *(uint32_t*)&h1;
    o.z = *(uint32_t*)&h2; o.w = *(uint32_t*)&h3;
    ((uint4*)dst)[i] = o;
}

__global__ __launch_bounds__(256)
void prep_misc(const float* __restrict__ Wout, const float* __restrict__ Wc,
               const float* __restrict__ Wp, const float* __restrict__ bc,
               const float* __restrict__ sib, const int* __restrict__ tokens,
               const float* __restrict__ emb, const float* __restrict__ Wg)
{
    const int bid = blockIdx.x, t = threadIdx.x;
    __shared__ double s[2][256];
    if (bid < PB_WOUT) {
        cvt8(Wout, g_WoutH, bid * 256 + t);
    } else if (bid < PB_WC) {
        cvt8(Wc, g_Wc_h, (bid - PB_WOUT) * 256 + t);
    } else if (bid < PB_WP) {
        cvt8(Wp, g_Wp_h, (bid - PB_WC) * 256 + t);
    } else if (bid < PB_W2) {
        int i = (bid - PB_WP) * 256 + t;
        int h = i >> 9, j = i & 511;
        g_W2h[i] = __float2half_rn(Wc[(size_t)h * 1024 + j] + Wc[(size_t)h * 1024 + 512 + j]);
        if (i < H_DIM)
            g_b2[i] = bc[i] + bc[512 + i] + SIB_SCALE_F * (sib[i] + sib[512 + i]);
    } else if (bid < PB_GATHER) {
        int i = (bid - PB_W2) * 256 + t;
        int n = i >> 6;
        int c = (i & 63) * 8;
        const float* src = emb + (size_t)tokens[n] * H_DIM + c;
        float4 a = *(const float4*)src;
        float4 b = *(const float4*)(src + 4);
        __half2 h0 = __floats2half2_rn(a.x, a.y);
        __half2 h1 = __floats2half2_rn(a.z, a.w);
        __half2 h2 = __floats2half2_rn(b.x, b.y);
        __half2 h3 = __floats2half2_rn(b.z, b.w);
        uint4 o;
        o.x = *(uint32_t*)&h0; o.y = *(uint32_t*)&h1;
        o.z = *(uint32_t*)&h2; o.w = *(uint32_t*)&h3;
        ((uint4*)(g_A0h + (size_t)n * H_DIM + c))[0] = o;
    } else {
        const int h = bid - PB_GATHER;
        double aL = 0.0, aR = 0.0;
        for (int j = t; j < H_DIM; j += 256) {
            double w = (double)Wg[j];
            aL += (double)Wc[(size_t)h * 1024 + j]       * w;
            aR += (double)Wc[(size_t)h * 1024 + 512 + j] * w;
        }
        s[0][t] = aL; s[1][t] = aR;
        __syncthreads();
        for (int st = 128; st > 0; st >>= 1) {
            if (t < st) { s[0][t] += s[0][t + st]; s[1][t] += s[1][t + st]; }
            __syncthreads();
        }
        if (t == 0) {
            g_uL[h] = (float)s[0][0];
            g_uR[h] = (float)s[1][0];
            g_bL[h] = bc[h]       + SIB_SCALE_F * sib[h];
            g_bR[h] = bc[512 + h] + SIB_SCALE_F * sib[512 + h];
        }
    }
}

__global__ __launch_bounds__(256)
void prep_g23(const float* __restrict__ Wc, const float* __restrict__ Wg,
              const float* __restrict__ Wp)
{
    const int bid = blockIdx.x, t = threadIdx.x;
    __shared__ double s[4][256];
    if (bid < H_DIM) {
        const int h = bid;
        double a3 = 0.0, a4 = 0.0, a5 = 0.0, a6 = 0.0;
        for (int j = t; j < H_DIM; j += 256) {
            double ul = (double)g_uL[j], ur = (double)g_uR[j];
            double wl = (double)Wc[(size_t)h * 1024 + j];
            double wr = (double)Wc[(size_t)h * 1024 + 512 + j];
            a3 += wl * ul; a4 += wl * ur; a5 += wr * ul; a6 += wr * ur;
        }
        s[0][t] = a3; s[1][t] = a4; s[2][t] = a5; s[3][t] = a6;
        __syncthreads();
        for (int st = 128; st > 0; st >>= 1) {
            if (t < st)
                #pragma unroll
                for (int q = 0; q < 4; q++) s[q][t] += s[q][t + st];
            __syncthreads();
        }
        if (t == 0) {
            g_cols[0][h] = Wg[h];
            g_cols[1][h] = g_uL[h];
            g_cols[2][h] = g_uR[h];
            g_cols[3][h] = (float)s[0][0];
            g_cols[4][h] = (float)s[1][0];
            g_cols[5][h] = (float)s[2][0];
            g_cols[6][h] = (float)s[3][0];
        }
    } else {
        const int e = bid - H_DIM;
        double a0 = 0.0, a1 = 0.0, a2 = 0.0;
        for (int h = t; h < H_DIM; h += 256) {
            double w = (double)Wp[(size_t)e * H_DIM + h];
            a0 += w * (double)Wg[h];
            a1 += w * (double)g_uL[h];
            a2 += w * (double)g_uR[h];
        }
        s[0][t] = a0; s[1][t] = a1; s[2][t] = a2;
        __syncthreads();
        for (int st = 128; st > 0; st >>= 1) {
            if (t < st)
                #pragma unroll
                for (int q = 0; q < 3; q++) s[q][t] += s[q][t + st];
            __syncthreads();
        }
        if (t == 0) {
            g_GG[0][e] = (float)s[0][0];
            g_GG[1][e] = (float)s[1][0];
            g_GG[2][e] = (float)s[2][0];
        }
    }
}

__global__ __launch_bounds__(256)
void prep_g3c(const float* __restrict__ Wp, const float* __restrict__ Wg,
              const float* __restrict__ dep, const float* __restrict__ bp)
{
    const int bid = blockIdx.x, t = threadIdx.x;
    if (bid < H_DIM) {
        const int e = bid;
        __shared__ double s4[4][256];
        double a[4] = {0, 0, 0, 0};
        for (int h = t; h < H_DIM; h += 256) {
            double w = (double)Wp[(size_t)e * H_DIM + h];
            #pragma unroll
            for (int i = 0; i < 4; i++) a[i] += w * (double)g_cols[3 + i][h];
        }
        #pragma unroll
        for (int i = 0; i < 4; i++) s4[i][t] = a[i];
        __syncthreads();
        for (int st = 128; st > 0; st >>= 1) {
            if (t < st)
                #pragma unroll
                for (int i = 0; i < 4; i++) s4[i][t] += s4[i][t + st];
            __syncthreads();
        }
        if (t == 0)
            #pragma unroll
            for (int i = 0; i < 4; i++) g_GG[3 + i][e] = (float)s4[i][0];
    } else {
        const int d = bid - H_DIM;
        __shared__ double s[256];
        const float* pa[16] = { dep, dep + 512, dep + 1024, g_bL, g_bR,
                                g_bL, g_bL, g_bR, g_bR,
                                bp, bp, bp, bp, bp, bp, bp };
        const float* pb[16] = { Wg, Wg, Wg, Wg, Wg,
                                g_uL, g_uR, g_uL, g_uR,
                                g_cols[0], g_cols[1], g_cols[2], g_cols[3],
                                g_cols[4], g_cols[5], g_cols[6] };
        double acc = 0.0;
        for (int c = t; c < H_DIM; c += 256)
            acc += (double)pa[d][c] * (double)pb[d][c];
        s[t] = acc;
        __syncthreads();
        for (int st = 128; st > 0; st >>= 1) {
            if (t < st) s[t] += s[t + st];
            __syncthreads();
        }
        if (t == 0) g_dots[d] = s[0];
    }
}

__global__ void prep_g4b(const float* __restrict__ bgp)
{
    if (threadIdx.x == 0) {
        const double de = (double)DEPTH_EMBED_SCALE;
        double bg = (double)bgp[0];
        const double* d = g_dots;
        g_kc[0] = de * d[0] + bg + d[9];
        g_kc[1] = d[3] + de * d[1] + bg + d[10];
        g_kc[2] = d[4] + de * d[1] + bg + d[11];
        g_kc[3] = d[5] + d[3] + de * d[2] + bg + d[12];
        g_kc[4] = d[6] + d[4] + de * d[2] + bg + d[13];
        g_kc[5] = d[7] + d[3] + de * d[2] + bg + d[14];
        g_kc[6] = d[8] + d[4] + de * d[2] + bg + d[15];
        g_cnt1 = 0; g_cnt2 = 0; g_cnt3 = 0;
    }
}

// ---------------------------------------------------------------------------
// Gate kernel: per-token double-precision gate dots (identical math to the
// previous pool), stores flags + inv count, and appends compaction lists.
// ---------------------------------------------------------------------------
__global__ __launch_bounds__(256)
void gate_kernel(const int* __restrict__ tokens, const float* __restrict__ emb)
{
    const int n = blockIdx.x;
    const int t = threadIdx.x;
    const float* a = emb + (size_t)tokens[n] * H_DIM;

    __shared__ double red[7][256];
    double p[7] = {0, 0, 0, 0, 0, 0, 0};
    for (int c = t; c < H_DIM; c += 256) {
        double av = (double)a[c];
        #pragma unroll
        for (int i = 0; i < 7; i++) p[i] += av * (double)g_GG[i][c];
    }
    #pragma unroll
    for (int i = 0; i < 7; i++) red[i][t] = p[i];
    __syncthreads();
    for (int s = 128; s > 0; s >>= 1) {
        if (t < s)
            #pragma unroll
            for (int i = 0; i < 7; i++) red[i][t] += red[i][t + s];
        __syncthreads();
    }

    if (t == 0) {
        const bool e0 = (red[0][0] + g_kc[0]) > 0.0;
        bool e1[2], e2[4];
        e1[0] = e0 && ((red[1][0] + g_kc[1]) > 0.0);
        e1[1] = e0 && ((red[2][0] + g_kc[2]) > 0.0);
        e2[0] = e1[0] && ((red[3][0] + g_kc[3]) > 0.0);
        e2[1] = e1[0] && ((red[4][0] + g_kc[4]) > 0.0);
        e2[2] = e1[1] && ((red[5][0] + g_kc[5]) > 0.0);
        e2[3] = e1[1] && ((red[6][0] + g_kc[6]) > 0.0);

        int f = 0;
        if (e0) {
            f |= 1;
            int pos = atomicAdd(&g_cnt1, 1);
            g_list1[pos] = make_int2(n, n);
        }
        #pragma unroll
        for (int j = 0; j < 2; j++) {
            if (e1[j]) {
                f |= 2 << j;
                int pos = atomicAdd(&g_cnt2, 1);
                g_list2[pos] = make_int2(2 * n + j, 2 * n + j);
            }
        }
        #pragma unroll
        for (int k = 0; k < 4; k++) {
            if (e2[k]) {
                f |= 8 << k;
                int pos = atomicAdd(&g_cnt3, 1);
                g_list3[pos] = make_int2(4 * n + k, 4 * n + k);
            }
        }
        float count = 1.f
            + 2.f * (e0 ? 1.f : 0.f)
            + 2.f * ((e1[0] ? 1.f : 0.f) + (e1[1] ? 1.f : 0.f))
            + 2.f * ((e2[0] ? 1.f : 0.f) + (e2[1] ? 1.f : 0.f) +
                     (e2[2] ? 1.f : 0.f) + (e2[3] ? 1.f : 0.f));
        g_flags[n] = f;
        g_inv[n]   = 1.f / fmaxf(count, 1e-8f);
    }
}

// Pad lists to multiples of 128; pads gather A row 0, scatter to overflow rows.
__global__ void pad_kernel()
{
    const int t = threadIdx.x;
    int c1n = g_cnt1, p1 = (c1n + 127) & ~127;
    for (int i = c1n + t; i < p1; i += 256) g_list1[i] = make_int2(0, N_TOK + (i - c1n));
    int c2n = g_cnt2, p2 = (c2n + 127) & ~127;
    for (int i = c2n + t; i < p2; i += 256) g_list2[i] = make_int2(0, 2 * N_TOK + (i - c2n));
    int c3n = g_cnt3, p3 = (c3n + 127) & ~127;
    for (int i = c3n + t; i < p3; i += 256) g_list3[i] = make_int2(0, 4 * N_TOK + (i - c3n));
    if (t == 0) { g_pc1 = p1; g_pc2 = p2; g_pc3 = p3; }
}

// ---------------------------------------------------------------------------
// ldmatrix / mma macros
// ---------------------------------------------------------------------------
#define LDSM_X4(r0, r1, r2, r3, addr) \
    asm volatile("ldmatrix.sync.aligned.m8n8.x4.shared.b16 {%0,%1,%2,%3}, [%4];" \
        : "=r"(r0), "=r"(r1), "=r"(r2), "=r"(r3) : "r"(addr))
#define LDSM_X4T(r0, r1, r2, r3, addr) \
    asm volatile("ldmatrix.sync.aligned.m8n8.x4.trans.shared.b16 {%0,%1,%2,%3}, [%4];" \
        : "=r"(r0), "=r"(r1), "=r"(r2), "=r"(r3) : "r"(addr))
#define HMMA16816(acc, a, b) \
    asm volatile("mma.sync.aligned.m16n8k16.row.col.f32.f16.f16.f32 " \
        "{%0,%1,%2,%3}, {%4,%5,%6,%7}, {%8,%9}, {%0,%1,%2,%3};" \
        : "+f"((acc)[0]), "+f"((acc)[1]), "+f"((acc)[2]), "+f"((acc)[3]) \
        : "r"((a)[0]), "r"((a)[1]), "r"((a)[2]), "r"((a)[3]), \
          "r"((b)[0]), "r"((b)[1]))

// ---------------------------------------------------------------------------
// Unified fp16 GEMM: 128x128, BK=32, 4-stage ring, single sync per k-iter,
// occ 2. GATHER=1: A rows from rows[].x, C rows to rows[].y; early-exit on
// padded count. MFAST=1: grid.x = M block.
// ---------------------------------------------------------------------------
#define AS_LD 40
#define BS_LD 136
#define AS4_STG  (128 * AS_LD * 2)
#define BS4_STG  (32 * BS_LD * 2)
#define SM4_B0   (4 * AS4_STG)
#define SM4_TOT  (4 * AS4_STG + 4 * BS4_STG)   // 75776 B

template<int EPI, int WF16, int MFAST, int GATHER>
__global__ __launch_bounds__(256, 2)
void gemm_f16(const __half* __restrict__ A, const __half* __restrict__ B,
              float* __restrict__ C, __half* __restrict__ C16,
              int M, int Ncol, int K,
              const float* __restrict__ bias, const float* __restrict__ sib,
              const int2* __restrict__ rows, const int* __restrict__ pcnt)
{
    extern __shared__ __half sm4[];

    const int tid  = threadIdx.x;
    const int row0 = (MFAST ? blockIdx.x : blockIdx.y) * 128;
    const int col0 = (MFAST ? blockIdx.y : blockIdx.x) * 128;
    if (GATHER) {
        if (row0 >= *pcnt) return;
    }
    const int warp = tid >> 5, lane = tid & 31;
    const int gid  = lane >> 2, tg = lane & 3;
    const int wm   = (warp & 1) * 64;
    const int wn   = (warp >> 1) * 32;

    const int ar = tid >> 1;
    const int ac = (tid & 1) * 16;
    const int br = tid >> 3;
    const int bc = (tid & 7) * 16;

    const int asrc = GATHER ? rows[row0 + ar].x : (row0 + ar);
    const __half* Ag = A + (size_t)asrc * (size_t)K + ac;
    const __half* Bg = B + (size_t)br * (size_t)Ncol + col0 + bc;

    __half* Asm = sm4;
    __half* Bsm = (__half*)((char*)sm4 + SM4_B0);

    const int a_r = lane & 15;
    const int a_c = (lane >> 4) << 3;
    const int b_k = (lane & 7) + (lane & 8);
    const int b_c = (lane >> 4) << 3;

    const uint32_t as_base = (uint32_t)__cvta_generic_to_shared(Asm);
    const uint32_t bs_base = (uint32_t)__cvta_generic_to_shared(Bsm);

    float acc[4][4][4];
    #pragma unroll
    for (int mi = 0; mi < 4; mi++)
        #pragma unroll
        for (int ni = 0; ni < 4; ni++)
            #pragma unroll
            for (int q = 0; q < 4; q++) acc[mi][ni][q] = 0.f;

    const int NT = K / 32;

    auto load_stage = [&](int kt, int buf) {
        const __half* Ap = Ag + (size_t)kt * 32;
        const __half* Bp = Bg + (size_t)kt * 32 * (size_t)Ncol;
        __half* Ad = Asm + buf * (128 * AS_LD) + ar * AS_LD + ac;
        __half* Bd = Bsm + buf * (32 * BS_LD) + br * BS_LD + bc;
        cp16(Ad,     Ap);
        cp16(Ad + 8, Ap + 8);
        cp16(Bd,     Bp);
        cp16(Bd + 8, Bp + 8);
        asm volatile("cp.async.commit_group;\n");
    };

    load_stage(0, 0);
    load_stage(1, 1);
    load_stage(2, 2);

    for (int kt = 0; kt < NT; kt++) {
        const int cur = kt & 3;
        if (kt + 2 < NT)      asm volatile("cp.async.wait_group 2;\n");
        else if (kt + 1 < NT) asm volatile("cp.async.wait_group 1;\n");
        else                  asm volatile("cp.async.wait_group 0;\n");
        __syncthreads();

        const uint32_t asb = as_base + cur * AS4_STG;
        const uint32_t bsb = bs_base + cur * BS4_STG;

        #pragma unroll
        for (int ks = 0; ks < 2; ks++) {
            const int kk = ks * 16;
            uint32_t af[4][4];
            #pragma unroll
            for (int mi = 0; mi < 4; mi++) {
                uint32_t ad = asb + ((wm + mi * 16 + a_r) * AS_LD + kk + a_c) * 2;
                LDSM_X4(af[mi][0], af[mi][1], af[mi][2], af[mi][3], ad);
            }
            uint32_t bf[4][2];
            #pragma unroll
            for (int j = 0; j < 2; j++) {
                uint32_t bd = bsb + ((kk + b_k) * BS_LD + wn + j * 16 + b_c) * 2;
                LDSM_X4T(bf[2 * j][0], bf[2 * j][1], bf[2 * j + 1][0], bf[2 * j + 1][1], bd);
            }
            #pragma unroll
            for (int mi = 0; mi < 4; mi++)
                #pragma unroll
                for (int ni = 0; ni < 4; ni++)
                    HMMA16816(acc[mi][ni], af[mi], bf[ni]);
        }

        if (kt + 3 < NT)
            load_stage(kt + 3, (kt + 3) & 3);
    }

    // destination rows
    int dstr[4][2];
    #pragma unroll
    for (int mi = 0; mi < 4; mi++) {
        int rb = row0 + wm + mi * 16 + gid;
        dstr[mi][0] = GATHER ? rows[rb].y     : rb;
        dstr[mi][1] = GATHER ? rows[rb + 8].y : rb + 8;
    }

    #pragma unroll
    for (int ni = 0; ni < 4; ni++) {
        int cc = col0 + wn + ni * 8 + tg * 2;
        float b0 = bias[cc], b1 = bias[cc + 1];
        if (EPI == 1) { b0 += SIB_SCALE_F * sib[cc]; b1 += SIB_SCALE_F * sib[cc + 1]; }
        #pragma unroll
        for (int mi = 0; mi < 4; mi++) {
            float v0 = acc[mi][ni][0] + b0, v1 = acc[mi][ni][1] + b1;
            float v2 = acc[mi][ni][2] + b0, v3 = acc[mi][ni][3] + b1;
            *(float2*)(C + (size_t)dstr[mi][0] * (size_t)Ncol + cc) = make_float2(v0, v1);
            *(float2*)(C + (size_t)dstr[mi][1] * (size_t)Ncol + cc) = make_float2(v2, v3);
            if (WF16) {
                *(__half2*)(C16 + (size_t)dstr[mi][0] * (size_t)Ncol + cc) = __floats2half2_rn(v0, v1);
                *(__half2*)(C16 + (size_t)dstr[mi][1] * (size_t)Ncol + cc) = __floats2half2_rn(v2, v3);
            }
        }
    }
}

// ---------------------------------------------------------------------------
// Pool kernel: reads stored flags + inv; masked sum (same order as before).
// ---------------------------------------------------------------------------
__global__ __launch_bounds__(256)
void pool_kernel()
{
    const int n = blockIdx.x;
    const int t = threadIdx.x;
    const float* H0 = g_h0 + (size_t)n * H_DIM;
    const float* C1 = g_c1 + (size_t)n * (2 * H_DIM);
    const float* C2 = g_c2 + (size_t)n * (4 * H_DIM);
    const float* D3 = g_d3 + (size_t)n * (4 * H_DIM);

    const int f = g_flags[n];
    const float inv = g_inv[n];
    const bool e0  = f & 1;
    const bool e10 = f & 2,  e11 = f & 4;
    const bool e20 = f & 8,  e21 = f & 16, e22 = f & 32, e23 = f & 64;

    for (int c = t; c < H_DIM; c += 256) {
        float s = H0[c];
        if (e0)  s += C1[c] + C1[H_DIM + c];
        if (e10) s += C2[c] + C2[H_DIM + c];
        if (e11) s += C2[2 * H_DIM + c] + C2[3 * H_DIM + c];
        if (e20) s += D3[0 * H_DIM + c];
        if (e21) s += D3[1 * H_DIM + c];
        if (e22) s += D3[2 * H_DIM + c];
        if (e23) s += D3[3 * H_DIM + c];
        g_pooled_h[(size_t)n * H_DIM + c] = __float2half_rn(s * inv);
    }
}

// ---------------------------------------------------------------------------
extern "C" void kernel_launch(void* const* d_in, const int* in_sizes, int n_in,
                              void* d_out, int out_size)
{
    const int*   tokens = (const int*)  d_in[0];
    const float* emb    = (const float*)d_in[1];
    const float* Wp     = (const float*)d_in[2];
    const float* bp     = (const float*)d_in[3];
    const float* Wc     = (const float*)d_in[4];
    const float* bc     = (const float*)d_in[5];
    const float* Wg     = (const float*)d_in[6];
    const float* bg     = (const float*)d_in[7];
    const float* dep    = (const float*)d_in[8];
    const float* sib    = (const float*)d_in[9];
    const float* Wout   = (const float*)d_in[10];
    const float* bout   = (const float*)d_in[11];
    float* out = (float*)d_out;

    float  *h0, *c1, *c2, *d3, *b2;
    __half *h0h, *c1h, *c2h, *pooledh, *A0h, *Wp_h, *Wc_h, *W2h, *Wout_h;
    int2   *l1, *l2, *l3;
    int    *pc1, *pc2, *pc3;
    cudaGetSymbolAddress((void**)&h0,      g_h0);
    cudaGetSymbolAddress((void**)&c1,      g_c1);
    cudaGetSymbolAddress((void**)&c2,      g_c2);
    cudaGetSymbolAddress((void**)&d3,      g_d3);
    cudaGetSymbolAddress((void**)&b2,      g_b2);
    cudaGetSymbolAddress((void**)&h0h,     g_h0h);
    cudaGetSymbolAddress((void**)&c1h,     g_c1h);
    cudaGetSymbolAddress((void**)&c2h,     g_c2h);
    cudaGetSymbolAddress((void**)&pooledh, g_pooled_h);
    cudaGetSymbolAddress((void**)&A0h,     g_A0h);
    cudaGetSymbolAddress((void**)&Wp_h,    g_Wp_h);
    cudaGetSymbolAddress((void**)&Wc_h,    g_Wc_h);
    cudaGetSymbolAddress((void**)&W2h,     g_W2h);
    cudaGetSymbolAddress((void**)&Wout_h,  g_WoutH);
    cudaGetSymbolAddress((void**)&l1,      g_list1);
    cudaGetSymbolAddress((void**)&l2,      g_list2);
    cudaGetSymbolAddress((void**)&l3,      g_list3);
    cudaGetSymbolAddress((void**)&pc1,     g_pc1);
    cudaGetSymbolAddress((void**)&pc2,     g_pc2);
    cudaGetSymbolAddress((void**)&pc3,     g_pc3);

    cudaFuncSetAttribute(gemm_f16<0, 1, 0, 0>, cudaFuncAttributeMaxDynamicSharedMemorySize, SM4_TOT);
    cudaFuncSetAttribute(gemm_f16<1, 1, 0, 1>, cudaFuncAttributeMaxDynamicSharedMemorySize, SM4_TOT);
    cudaFuncSetAttribute(gemm_f16<0, 0, 0, 1>, cudaFuncAttributeMaxDynamicSharedMemorySize, SM4_TOT);
    cudaFuncSetAttribute(gemm_f16<0, 0, 1, 0>, cudaFuncAttributeMaxDynamicSharedMemorySize, SM4_TOT);

    dim3 blk(256);

    // Preps + gate flags + compaction lists
    prep_misc<<<PB_G1, blk>>>(Wout, Wc, Wp, bc, sib, tokens, emb, Wg);
    prep_g23<<<2 * H_DIM, blk>>>(Wc, Wg, Wp);
    prep_g3c<<<H_DIM + 16, blk>>>(Wp, Wg, dep, bp);
    prep_g4b<<<1, 32>>>(bg);
    gate_kernel<<<N_TOK, blk>>>(tokens, emb);
    pad_kernel<<<1, blk>>>();

    // h0 (ungated)
    gemm_f16<0, 1, 0, 0><<<dim3(H_DIM / 128, N_TOK / 128), blk, SM4_TOT>>>(
        A0h, Wp_h, h0, h0h, N_TOK, H_DIM, H_DIM, bp, nullptr, nullptr, nullptr);
    // c1 over active tokens (worst-case grid, early-exit)
    gemm_f16<1, 1, 0, 1><<<dim3(1024 / 128, N_TOK / 128), blk, SM4_TOT>>>(
        h0h, Wc_h, c1, c1h, N_TOK, 1024, H_DIM, bc, sib, l1, pc1);
    // c2 over active depth-1 children
    gemm_f16<1, 1, 0, 1><<<dim3(1024 / 128, (2 * N_TOK) / 128), blk, SM4_TOT>>>(
        c1h, Wc_h, c2, c2h, 2 * N_TOK, 1024, H_DIM, bc, sib, l2, pc2);
    // d3 pair sums over active depth-2 children
    gemm_f16<0, 0, 0, 1><<<dim3(H_DIM / 128, (4 * N_TOK) / 128), blk, SM4_TOT>>>(
        c2h, W2h, d3, nullptr, 4 * N_TOK, H_DIM, H_DIM, b2, nullptr, l3, pc3);

    // masked pooling from stored flags
    pool_kernel<<<N_TOK, blk>>>();

    // logits: proven tiled kernel, grid x=M (B-tile L2 sharing), y=N
    gemm_f16<0, 0, 1, 0><<<dim3(N_TOK / 128, V_DIM / 128), blk, SM4_TOT>>>(
        pooledh, Wout_h, out, nullptr, N_TOK, V_DIM, H_DIM, bout, nullptr, nullptr, nullptr);
}